// round 5
// baseline (speedup 1.0000x reference)
#include <cuda_runtime.h>
#include <cuda_fp16.h>
#include <cstdint>

#define BB   128
#define TT   256
#define NN   100
#define SS   7
#define GG   16
#define FF   35
#define FP   36   // padded H1 row stride in lm kernel

typedef unsigned long long ull;

// gi scratch: [n][t][g48][b128] fp16  (157 MB x2 traffic)
__device__ __half g_gi[(size_t)NN * TT * 48 * BB];

__device__ __forceinline__ ull fma2(ull a, ull b, ull c) {
    ull d; asm("fma.rn.f32x2 %0, %1, %2, %3;" : "=l"(d) : "l"(a), "l"(b), "l"(c));
    return d;
}
__device__ __forceinline__ ull dup2(float w) {
    ull d; asm("mov.b64 %0, {%1, %1};" : "=l"(d) : "f"(w));
    return d;
}
__device__ __forceinline__ ull pack2(float lo, float hi) {
    ull d; asm("mov.b64 %0, {%1, %2};" : "=l"(d) : "f"(lo), "f"(hi));
    return d;
}
__device__ __forceinline__ float plo(ull p) { return __int_as_float((int)(unsigned)p); }
__device__ __forceinline__ float phi(ull p) { return __int_as_float((int)(p >> 32)); }

__device__ __forceinline__ float sigf(float x) {
    return __fdividef(1.0f, 1.0f + __expf(-x));
}
__device__ __forceinline__ float tanhfast(float x) {
    return __fdividef(2.0f, 1.0f + __expf(-2.0f * x)) - 1.0f;
}

__device__ __forceinline__ void cpasync4(uint32_t saddr, const float* gptr, int vbytes) {
    asm volatile("cp.async.ca.shared.global [%0], [%1], 4, %2;"
                 :: "r"(saddr), "l"(gptr), "r"(vbytes));
}
__device__ __forceinline__ void cpcommit() {
    asm volatile("cp.async.commit_group;");
}
__device__ __forceinline__ void cpwait0() {
    asm volatile("cp.async.wait_group 0;");
}

// ============================================================================
// Kernel A: gi GEMM -> g_gi[n][t][g][b] fp16.
// grid (16 tchunks of 16t, 100 n), 128 threads = 8 gg(6 gates) x 16 bpg(8 b).
// No transpose: accumulators store directly coalesced as half2.
// ============================================================================
#define ACH 16
#define XROW 130

__global__ void __launch_bounds__(128) gi_gemm_kernel(
    const float* __restrict__ x,
    const float* __restrict__ Wih)
{
    extern __shared__ __align__(16) float smraw[];
    float* wd = smraw;               // [35][48]
    float* xs = wd + 35 * 48;        // [2][35][XROW]

    const int n   = blockIdx.y;
    const int t0  = blockIdx.x * ACH;
    const int tid = threadIdx.x;
    const int gg  = tid >> 4;     // 0..7  (6 gates each)
    const int bpg = tid & 15;     // 0..15 (batch pairs at 2bpg+32p)

    // stage weights once: Wih[n][g][f] -> wd[f*48 + g]
    const float* Wg = Wih + (size_t)n * 48 * FF;
    for (int i = tid; i < 48 * FF; i += 128)
        wd[(i % FF) * 48 + (i / FF)] = Wg[i];

    // staging: thread (s = tid%7, q = tid/7 in 0..15), 112 active
    const int offs[5] = {0, -10, 1, 10, -1};
    const int s  = tid % 7;
    const int q  = tid / 7;
    const bool active = (q < 16);
    int nofs[5]; int vbytes[5];
    #pragma unroll
    for (int o = 0; o < 5; o++) {
        int n2 = n + offs[o];
        bool v = (n2 >= 0) && (n2 < NN);
        nofs[o]   = (v ? n2 : 0) * SS + s;
        vbytes[o] = v ? 4 : 0;
    }
    uint32_t xs_base = (uint32_t)__cvta_generic_to_shared(xs);

    auto stage = [&](int buf, int t) {
        if (active) {
            #pragma unroll
            for (int o = 0; o < 5; o++) {
                int f = o * 7 + s;
                #pragma unroll
                for (int bc = 0; bc < 8; bc++) {
                    int b = bc * 16 + q;
                    const float* gp = x + (size_t)b * (TT * NN * SS)
                                        + (size_t)t * (NN * SS) + nofs[o];
                    uint32_t sa = xs_base + (uint32_t)((buf * 35 * XROW + f * XROW + b) * 4);
                    cpasync4(sa, gp, vbytes[o]);
                }
            }
        }
        cpcommit();
    };

    stage(0, t0);
    cpwait0();
    __syncthreads();

    for (int tt = 0; tt < ACH; tt++) {
        const int t   = t0 + tt;
        const int cur = tt & 1;

        if (tt < ACH - 1) stage(cur ^ 1, t + 1);

        const float* xc = xs + cur * 35 * XROW;
        ull acc[6][4];
        #pragma unroll
        for (int g = 0; g < 6; g++)
            #pragma unroll
            for (int p = 0; p < 4; p++) acc[g][p] = 0ULL;

        #pragma unroll 5
        for (int f = 0; f < FF; f++) {
            const ull* xp = reinterpret_cast<const ull*>(&xc[f * XROW]);
            ull x0 = xp[bpg     ];
            ull x1 = xp[bpg + 16];
            ull x2 = xp[bpg + 32];
            ull x3 = xp[bpg + 48];
            const float* wp = &wd[f * 48 + gg * 6];
            #pragma unroll
            for (int g = 0; g < 6; g++) {
                ull wv = dup2(wp[g]);
                acc[g][0] = fma2(x0, wv, acc[g][0]);
                acc[g][1] = fma2(x1, wv, acc[g][1]);
                acc[g][2] = fma2(x2, wv, acc[g][2]);
                acc[g][3] = fma2(x3, wv, acc[g][3]);
            }
        }

        // direct coalesced store: gi[n][t][g][b] as half2 (batches 2bpg+32p, +1)
        __half2* grow = reinterpret_cast<__half2*>(
            g_gi + ((size_t)(n * TT + t) * 48 + gg * 6) * BB);
        #pragma unroll
        for (int g = 0; g < 6; g++) {
            #pragma unroll
            for (int p = 0; p < 4; p++) {
                grow[(size_t)g * 64 + bpg + 16 * p] =
                    __floats2half2_rn(plo(acc[g][p]), phi(acc[g][p]));
            }
        }

        cpwait0();
        __syncthreads();
    }
}

// ============================================================================
// Kernel C: recurrence + sc MLP. grid (4 bblk of 32 batches, 100 n), 512 thr.
// Warp = gate j (16 warps); lane = batch. Whh warp-uniform in registers.
// r/z packed in fma2; one syncthreads per step; gi(t+1) prefetched.
// ============================================================================
__global__ void __launch_bounds__(512) gru_rec_kernel(
    const float* __restrict__ Whh,
    const float* __restrict__ bih, const float* __restrict__ bhh,
    const float* __restrict__ scW1, const float* __restrict__ scb1,
    const float* __restrict__ scW2, const float* __restrict__ scb2,
    const float* __restrict__ scW3, const float* __restrict__ scb3,
    float* __restrict__ out)
{
    __shared__ __align__(16) float hsm[2][GG][33];

    const int n    = blockIdx.y;
    const int bblk = blockIdx.x;
    const int tid  = threadIdx.x;
    const int j    = tid >> 5;    // warp = gate j
    const int b    = tid & 31;    // lane = batch
    const int bglob = bblk * 32 + b;

    // Whh rows j (r), j+16 (z), j+32 (n) — warp-uniform
    const float* wrp = Whh + ((size_t)n * 48 + j     ) * GG;
    const float* wzp = Whh + ((size_t)n * 48 + j + 16) * GG;
    const float* wnp = Whh + ((size_t)n * 48 + j + 32) * GG;
    ull   wrz[GG];
    float wnn[GG];
    #pragma unroll
    for (int k = 0; k < GG; k++) {
        wrz[k] = pack2(wrp[k], wzp[k]);
        wnn[k] = wnp[k];
    }
    const float br  = bih[n * 48 + j     ] + bhh[n * 48 + j     ];
    const float bz  = bih[n * 48 + j + 16] + bhh[n * 48 + j + 16];
    const float bin = bih[n * 48 + j + 32];
    const float bhn = bhh[n * 48 + j + 32];

    hsm[0][j][b] = 0.0f;
    float hreg = 0.0f;
    __syncthreads();

    const __half* gbase = g_gi + (size_t)n * TT * 48 * BB + bglob;
    // prefetch t = 0
    float gr = __half2float(gbase[(size_t)(j     ) * BB]);
    float gz = __half2float(gbase[(size_t)(j + 16) * BB]);
    float gn = __half2float(gbase[(size_t)(j + 32) * BB]);

    int cur = 0;
    for (int t = 0; t < TT; t++) {
        const __half* gnext = gbase + (size_t)((t + 1 < TT) ? t + 1 : t) * 48 * BB;
        float pgr = __half2float(gnext[(size_t)(j     ) * BB]);
        float pgz = __half2float(gnext[(size_t)(j + 16) * BB]);
        float pgn = __half2float(gnext[(size_t)(j + 32) * BB]);

        ull   arz = pack2(br + gr, bz + gz);
        float hn  = bhn;
        const float* hc = &hsm[cur][0][0];
        #pragma unroll
        for (int k = 0; k < GG; k++) {
            float hk = hc[k * 33 + b];
            arz = fma2(dup2(hk), wrz[k], arz);
            hn  = fmaf(hk, wnn[k], hn);
        }
        float r  = sigf(plo(arz));
        float z  = sigf(phi(arz));
        float nv = tanhfast(bin + gn + r * hn);
        float hnew = nv + z * (hreg - nv);
        hreg = hnew;
        hsm[cur ^ 1][j][b] = hnew;
        __syncthreads();
        gr = pgr; gz = pgz; gn = pgn;
        cur ^= 1;
    }
    // hT in hsm[0] (T even)

    // sc MLP epilogue
    {
        float a = scb1[n * GG + j];
        #pragma unroll
        for (int k = 0; k < GG; k++)
            a = fmaf(hsm[0][k][b], scW1[((size_t)n * GG + k) * GG + j], a);
        __syncthreads();
        hsm[1][j][b] = fmaxf(a, 0.0f);
    }
    __syncthreads();
    {
        float a = scb2[n * GG + j];
        #pragma unroll
        for (int k = 0; k < GG; k++)
            a = fmaf(hsm[1][k][b], scW2[((size_t)n * GG + k) * GG + j], a);
        __syncthreads();
        hsm[0][j][b] = fmaxf(a, 0.0f);
    }
    __syncthreads();
    if (j == 0) {
        float q = scb3[n];
        #pragma unroll
        for (int k = 0; k < GG; k++)
            q = fmaf(hsm[0][k][b], scW3[n * GG + k], q);
        int idx = n * BB + bglob;
        out[idx] = out[idx] + q;   // lm kernel already wrote f
    }
}

// ============================================================================
// Kernel B: lm MLP on xl = gather(x[:, T-1]) -> WRITES f into out[n*B + b]
// ============================================================================
__global__ void __launch_bounds__(256) lm_mlp_kernel(
    const float* __restrict__ x,
    const float* __restrict__ W1, const float* __restrict__ b1,
    const float* __restrict__ W2, const float* __restrict__ b2,
    const float* __restrict__ W3, const float* __restrict__ b3,
    float* __restrict__ out)
{
    extern __shared__ __align__(16) float H1T[];      // [512][36]
    __shared__ __align__(16) float xlsT[FF][32];
    __shared__ __align__(16) float H2s[32][257];
    __shared__ float sp[8][32];

    const int n    = blockIdx.y;
    const int bblk = blockIdx.x;
    const int tid  = threadIdx.x;
    const int offs[5] = {0, -10, 1, 10, -1};

    for (int idx = tid; idx < FF * 32; idx += 256) {
        int f = idx / 32, b = idx % 32;
        int o = f / SS, sx = f % SS;
        int n2 = n + offs[o];
        float v = 0.0f;
        if (n2 >= 0 && n2 < NN) {
            size_t gb = (size_t)(bblk * 32 + b);
            v = x[(gb * TT + (TT - 1)) * (NN * SS) + n2 * SS + sx];
        }
        xlsT[f][b] = v;
    }
    __syncthreads();

    // layer 1: 8h x 8b f32x2 tile
    {
        const float* W1g = W1 + (size_t)n * FF * 512;
        const float* b1g = b1 + (size_t)n * 512;
        const int bg = tid >> 6;
        const int hg = tid & 63;
        ull acc[8][4];
        #pragma unroll
        for (int h = 0; h < 8; h++)
            #pragma unroll
            for (int p = 0; p < 4; p++) acc[h][p] = 0ULL;
        #pragma unroll 5
        for (int f = 0; f < FF; f++) {
            const float4* wv = reinterpret_cast<const float4*>(W1g + f * 512 + hg * 8);
            float4 wa = wv[0], wb = wv[1];
            ull wdp[8] = {dup2(wa.x), dup2(wa.y), dup2(wa.z), dup2(wa.w),
                          dup2(wb.x), dup2(wb.y), dup2(wb.z), dup2(wb.w)};
            const ull* xp = reinterpret_cast<const ull*>(&xlsT[f][bg * 8]);
            ull x0 = xp[0], x1 = xp[1], x2 = xp[2], x3 = xp[3];
            #pragma unroll
            for (int h = 0; h < 8; h++) {
                acc[h][0] = fma2(x0, wdp[h], acc[h][0]);
                acc[h][1] = fma2(x1, wdp[h], acc[h][1]);
                acc[h][2] = fma2(x2, wdp[h], acc[h][2]);
                acc[h][3] = fma2(x3, wdp[h], acc[h][3]);
            }
        }
        #pragma unroll
        for (int h = 0; h < 8; h++) {
            float bias = b1g[hg * 8 + h];
            float* row = &H1T[(hg * 8 + h) * FP + bg * 8];
            float4 v0, v1;
            v0.x = fmaxf(plo(acc[h][0]) + bias, 0.0f);
            v0.y = fmaxf(phi(acc[h][0]) + bias, 0.0f);
            v0.z = fmaxf(plo(acc[h][1]) + bias, 0.0f);
            v0.w = fmaxf(phi(acc[h][1]) + bias, 0.0f);
            v1.x = fmaxf(plo(acc[h][2]) + bias, 0.0f);
            v1.y = fmaxf(phi(acc[h][2]) + bias, 0.0f);
            v1.z = fmaxf(plo(acc[h][3]) + bias, 0.0f);
            v1.w = fmaxf(phi(acc[h][3]) + bias, 0.0f);
            reinterpret_cast<float4*>(row)[0] = v0;
            reinterpret_cast<float4*>(row)[1] = v1;
        }
    }
    __syncthreads();

    // layer 2: 4h x 8b f32x2 tile
    {
        const float4* W2g = reinterpret_cast<const float4*>(W2 + (size_t)n * 512 * 256);
        const float*  b2g = b2 + (size_t)n * 256;
        const int hg = tid & 63;
        const int bg = tid >> 6;
        ull acc[16];
        #pragma unroll
        for (int i = 0; i < 16; i++) acc[i] = 0ULL;
        #pragma unroll 4
        for (int f = 0; f < 512; f++) {
            float4 wv = W2g[f * 64 + hg];
            ull wdp[4] = {dup2(wv.x), dup2(wv.y), dup2(wv.z), dup2(wv.w)};
            const ull* xp = reinterpret_cast<const ull*>(&H1T[f * FP + bg * 8]);
            ull x0 = xp[0], x1 = xp[1], x2 = xp[2], x3 = xp[3];
            #pragma unroll
            for (int hh = 0; hh < 4; hh++) {
                acc[hh*4+0] = fma2(x0, wdp[hh], acc[hh*4+0]);
                acc[hh*4+1] = fma2(x1, wdp[hh], acc[hh*4+1]);
                acc[hh*4+2] = fma2(x2, wdp[hh], acc[hh*4+2]);
                acc[hh*4+3] = fma2(x3, wdp[hh], acc[hh*4+3]);
            }
        }
        #pragma unroll
        for (int hh = 0; hh < 4; hh++) {
            float bias = b2g[hg * 4 + hh];
            #pragma unroll
            for (int pi = 0; pi < 4; pi++) {
                int b = bg * 8 + pi * 2;
                H2s[b    ][hg * 4 + hh] = fmaxf(plo(acc[hh*4+pi]) + bias, 0.0f);
                H2s[b + 1][hg * 4 + hh] = fmaxf(phi(acc[hh*4+pi]) + bias, 0.0f);
            }
        }
    }
    __syncthreads();

    // layer 3
    {
        const float* W3g = W3 + (size_t)n * 256;
        int b = tid & 31, seg = tid >> 5;
        float sacc = 0.0f;
        #pragma unroll
        for (int c = 0; c < 32; c++)
            sacc = fmaf(H2s[b][seg * 32 + c], W3g[seg * 32 + c], sacc);
        sp[seg][b] = sacc;
    }
    __syncthreads();
    if (tid < 32) {
        float tot = b3[n];
        #pragma unroll
        for (int seg = 0; seg < 8; seg++) tot += sp[seg][tid];
        out[n * BB + bblk * 32 + tid] = tot;
    }
}

// ============================================================================
extern "C" void kernel_launch(void* const* d_in, const int* in_sizes, int n_in,
                              void* d_out, int out_size) {
    const float* x      = (const float*)d_in[0];
    const float* lm_W1  = (const float*)d_in[1];
    const float* lm_b1  = (const float*)d_in[2];
    const float* lm_W2  = (const float*)d_in[3];
    const float* lm_b2  = (const float*)d_in[4];
    const float* lm_W3  = (const float*)d_in[5];
    const float* lm_b3  = (const float*)d_in[6];
    const float* gWih   = (const float*)d_in[7];
    const float* gWhh   = (const float*)d_in[8];
    const float* gbih   = (const float*)d_in[9];
    const float* gbhh   = (const float*)d_in[10];
    const float* scW1   = (const float*)d_in[11];
    const float* scb1   = (const float*)d_in[12];
    const float* scW2   = (const float*)d_in[13];
    const float* scb2   = (const float*)d_in[14];
    const float* scW3   = (const float*)d_in[15];
    const float* scb3   = (const float*)d_in[16];
    float* out = (float*)d_out;

    const int h1t_bytes = 512 * FP * 4;                 // 73728
    const int a_bytes   = (35*48 + 2*35*XROW) * 4;      // 43120
    cudaFuncSetAttribute(lm_mlp_kernel,
                         cudaFuncAttributeMaxDynamicSharedMemorySize, h1t_bytes);
    cudaFuncSetAttribute(gi_gemm_kernel,
                         cudaFuncAttributeMaxDynamicSharedMemorySize, a_bytes);

    // A: gi GEMM
    dim3 gridA(TT / ACH, NN), blockA(128);
    gi_gemm_kernel<<<gridA, blockA, a_bytes>>>(x, gWih);

    // B: lm MLP (writes out)
    dim3 gridB(4, NN), blockB(256);
    lm_mlp_kernel<<<gridB, blockB, h1t_bytes>>>(
        x, lm_W1, lm_b1, lm_W2, lm_b2, lm_W3, lm_b3, out);

    // C: recurrence (reads gi, adds to out)
    dim3 gridC(4, NN), blockC(512);
    gru_rec_kernel<<<gridC, blockC>>>(
        gWhh, gbih, gbhh,
        scW1, scb1, scW2, scb2, scW3, scb3, out);
}

// round 6
// speedup vs baseline: 1.1325x; 1.1325x over previous
#include <cuda_runtime.h>
#include <cuda_fp16.h>
#include <cstdint>

#define BB   128
#define TT   256
#define NN   100
#define SS   7
#define GG   16
#define FF   35
#define FP   36   // padded H1 row stride in lm kernel

typedef unsigned long long ull;

// gi scratch: [n][t][b][48] fp16  (157 MB)
__device__ __half g_gi[(size_t)NN * TT * BB * 48];

__device__ __forceinline__ ull fma2(ull a, ull b, ull c) {
    ull d; asm("fma.rn.f32x2 %0, %1, %2, %3;" : "=l"(d) : "l"(a), "l"(b), "l"(c));
    return d;
}
__device__ __forceinline__ ull dup2(float w) {
    ull d; asm("mov.b64 %0, {%1, %1};" : "=l"(d) : "f"(w));
    return d;
}
__device__ __forceinline__ float plo(ull p) { return __int_as_float((int)(unsigned)p); }
__device__ __forceinline__ float phi(ull p) { return __int_as_float((int)(p >> 32)); }

__device__ __forceinline__ float sigf(float x) {
    return __fdividef(1.0f, 1.0f + __expf(-x));
}
__device__ __forceinline__ float tanhfast(float x) {
    return __fdividef(2.0f, 1.0f + __expf(-2.0f * x)) - 1.0f;
}

__device__ __forceinline__ void cpasync4(uint32_t saddr, const float* gptr, int vbytes) {
    asm volatile("cp.async.ca.shared.global [%0], [%1], 4, %2;"
                 :: "r"(saddr), "l"(gptr), "r"(vbytes));
}
__device__ __forceinline__ void cpcommit() {
    asm volatile("cp.async.commit_group;");
}
__device__ __forceinline__ void cpwait0() {
    asm volatile("cp.async.wait_group 0;");
}

// ============================================================================
// Kernel A: gi GEMM -> g_gi[n][t][b][48] fp16, NO transpose.
// 128 threads = 8 jq(6 j's) x 16 bq(8 batches). acc pairs packed along j.
// ============================================================================
#define ACH 16
#define XROW 132   // padded xs row, 16B-aligned stride

__global__ void __launch_bounds__(128) gi_gemm_kernel(
    const float* __restrict__ x,
    const float* __restrict__ Wih)
{
    extern __shared__ __align__(16) float smraw[];
    float* wd = smraw;               // [35][48], j consecutive
    float* xs = wd + 35 * 48;        // [2][35][XROW]

    const int n   = blockIdx.y;
    const int t0  = blockIdx.x * ACH;
    const int tid = threadIdx.x;
    const int jq  = tid >> 4;     // 0..7: owns j = jq*6 .. jq*6+5
    const int bq  = tid & 15;     // 0..15: owns b = bq*8 .. bq*8+7

    // stage weights once: Wih[n][g][f] -> wd[f*48 + g]
    const float* Wg = Wih + (size_t)n * 48 * FF;
    for (int i = tid; i < 48 * FF; i += 128)
        wd[(i % FF) * 48 + (i / FF)] = Wg[i];

    // staging: thread (s = tid%7, q = tid/7 in 0..15), 112 active
    const int offs[5] = {0, -10, 1, 10, -1};
    const int s  = tid % 7;
    const int q  = tid / 7;
    const bool active = (q < 16);
    int nofs[5]; int vbytes[5];
    #pragma unroll
    for (int o = 0; o < 5; o++) {
        int n2 = n + offs[o];
        bool v = (n2 >= 0) && (n2 < NN);
        nofs[o]   = (v ? n2 : 0) * SS + s;
        vbytes[o] = v ? 4 : 0;
    }
    uint32_t xs_base = (uint32_t)__cvta_generic_to_shared(xs);

    auto stage = [&](int buf, int t) {
        if (active) {
            #pragma unroll
            for (int o = 0; o < 5; o++) {
                int f = o * 7 + s;
                #pragma unroll
                for (int bc = 0; bc < 8; bc++) {
                    int b = bc * 16 + q;
                    const float* gp = x + (size_t)b * (TT * NN * SS)
                                        + (size_t)t * (NN * SS) + nofs[o];
                    uint32_t sa = xs_base + (uint32_t)((buf * 35 * XROW + f * XROW + b) * 4);
                    cpasync4(sa, gp, vbytes[o]);
                }
            }
        }
        cpcommit();
    };

    stage(0, t0);
    cpwait0();
    __syncthreads();

    for (int tt = 0; tt < ACH; tt++) {
        const int t   = t0 + tt;
        const int cur = tt & 1;

        if (tt < ACH - 1) stage(cur ^ 1, t + 1);

        const float* xc = xs + cur * 35 * XROW;
        ull acc[3][8];
        #pragma unroll
        for (int jp = 0; jp < 3; jp++)
            #pragma unroll
            for (int b = 0; b < 8; b++) acc[jp][b] = 0ULL;

        #pragma unroll 5
        for (int f = 0; f < FF; f++) {
            const float4* xp = reinterpret_cast<const float4*>(&xc[f * XROW + bq * 8]);
            float4 xa = xp[0], xb = xp[1];
            ull xd[8] = {dup2(xa.x), dup2(xa.y), dup2(xa.z), dup2(xa.w),
                         dup2(xb.x), dup2(xb.y), dup2(xb.z), dup2(xb.w)};
            const ull* wp = reinterpret_cast<const ull*>(&wd[f * 48 + jq * 6]);
            ull w0 = wp[0], w1 = wp[1], w2 = wp[2];
            #pragma unroll
            for (int b = 0; b < 8; b++) {
                acc[0][b] = fma2(xd[b], w0, acc[0][b]);
                acc[1][b] = fma2(xd[b], w1, acc[1][b]);
                acc[2][b] = fma2(xd[b], w2, acc[2][b]);
            }
        }

        // direct store: gi[n][t][b][48]; thread covers j = jq*6..+5 for 8 b's
        __half* gout = g_gi + ((size_t)(n * TT + t) * BB) * 48 + jq * 6;
        #pragma unroll
        for (int b = 0; b < 8; b++) {
            __half2* dst = reinterpret_cast<__half2*>(gout + (size_t)(bq * 8 + b) * 48);
            dst[0] = __floats2half2_rn(plo(acc[0][b]), phi(acc[0][b]));
            dst[1] = __floats2half2_rn(plo(acc[1][b]), phi(acc[1][b]));
            dst[2] = __floats2half2_rn(plo(acc[2][b]), phi(acc[2][b]));
        }

        cpwait0();
        __syncthreads();
    }
}

// ============================================================================
// Kernel C: recurrence + sc MLP. grid (16 bblk of 8 batches, 100 n), 128 thr.
// Warp owns 2 batches; lane = (j in 16, bh in 2). Whh in regs, __syncwarp only.
// ============================================================================
__global__ void __launch_bounds__(128) gru_rec_kernel(
    const float* __restrict__ Whh,
    const float* __restrict__ bih, const float* __restrict__ bhh,
    const float* __restrict__ scW1, const float* __restrict__ scb1,
    const float* __restrict__ scW2, const float* __restrict__ scb2,
    const float* __restrict__ scW3, const float* __restrict__ scb3,
    float* __restrict__ out)
{
    __shared__ __align__(16) float shf[4][2][2][16];  // [warp][buf][bh][k]

    const int n    = blockIdx.y;
    const int bblk = blockIdx.x;
    const int tid  = threadIdx.x;
    const int w    = tid >> 5;
    const int lane = tid & 31;
    const int j    = lane & 15;
    const int bh   = lane >> 4;
    const int bglob = bblk * 8 + w * 2 + bh;

    const ull* wrp = reinterpret_cast<const ull*>(Whh + ((size_t)n * 48 + j     ) * GG);
    const ull* wzp = reinterpret_cast<const ull*>(Whh + ((size_t)n * 48 + j + 16) * GG);
    const ull* wnp = reinterpret_cast<const ull*>(Whh + ((size_t)n * 48 + j + 32) * GG);
    ull wr[8], wz[8], wn[8];
    #pragma unroll
    for (int k = 0; k < 8; k++) { wr[k] = wrp[k]; wz[k] = wzp[k]; wn[k] = wnp[k]; }

    const float br  = bih[n * 48 + j     ] + bhh[n * 48 + j     ];
    const float bz  = bih[n * 48 + j + 16] + bhh[n * 48 + j + 16];
    const float bin = bih[n * 48 + j + 32];
    const float bhn = bhh[n * 48 + j + 32];

    shf[w][0][bh][j] = 0.0f;
    float hreg = 0.0f;
    __syncwarp();

    const __half* gbase = g_gi + ((size_t)n * TT * BB + bglob) * 48;
    float gir = __half2float(gbase[j]);
    float giz = __half2float(gbase[j + 16]);
    float gin = __half2float(gbase[j + 32]);

    int cur = 0;
    for (int t = 0; t < TT; t++) {
        // prefetch next t (clamped) — hides DRAM latency behind compute
        const __half* grn = gbase + (size_t)((t + 1 < TT) ? t + 1 : t) * BB * 48;
        float pgr = __half2float(grn[j]);
        float pgz = __half2float(grn[j + 16]);
        float pgn = __half2float(grn[j + 32]);

        const ull* hp = reinterpret_cast<const ull*>(&shf[w][cur][bh][0]);
        ull ar = 0ULL, az = 0ULL, an = 0ULL;
        #pragma unroll
        for (int k = 0; k < 8; k++) {
            ull hk = hp[k];
            ar = fma2(hk, wr[k], ar);
            az = fma2(hk, wz[k], az);
            an = fma2(hk, wn[k], an);
        }
        float r  = sigf(br + gir + plo(ar) + phi(ar));
        float z  = sigf(bz + giz + plo(az) + phi(az));
        float nv = tanhfast(bin + gin + r * (bhn + plo(an) + phi(an)));
        float hnew = nv + z * (hreg - nv);
        hreg = hnew;
        shf[w][cur ^ 1][bh][j] = hnew;
        __syncwarp();
        gir = pgr; giz = pgz; gin = pgn;
        cur ^= 1;
    }

    // sc MLP epilogue
    shf[w][0][bh][j] = hreg;
    __syncwarp();
    {
        float a = scb1[n * GG + j];
        #pragma unroll
        for (int k = 0; k < GG; k++)
            a = fmaf(shf[w][0][bh][k], scW1[((size_t)n * GG + k) * GG + j], a);
        shf[w][1][bh][j] = fmaxf(a, 0.0f);
    }
    __syncwarp();
    {
        float a = scb2[n * GG + j];
        #pragma unroll
        for (int k = 0; k < GG; k++)
            a = fmaf(shf[w][1][bh][k], scW2[((size_t)n * GG + k) * GG + j], a);
        shf[w][0][bh][j] = fmaxf(a, 0.0f);
    }
    __syncwarp();
    if (j == 0) {
        float q = scb3[n];
        #pragma unroll
        for (int k = 0; k < GG; k++)
            q = fmaf(shf[w][0][bh][k], scW3[n * GG + k], q);
        int idx = n * BB + bglob;
        out[idx] = out[idx] + q;   // lm kernel already wrote f
    }
}

// ============================================================================
// Kernel B: lm MLP on xl = gather(x[:, T-1]) -> WRITES f into out[n*B + b]
// ============================================================================
__global__ void __launch_bounds__(256) lm_mlp_kernel(
    const float* __restrict__ x,
    const float* __restrict__ W1, const float* __restrict__ b1,
    const float* __restrict__ W2, const float* __restrict__ b2,
    const float* __restrict__ W3, const float* __restrict__ b3,
    float* __restrict__ out)
{
    extern __shared__ __align__(16) float H1T[];      // [512][36]
    __shared__ __align__(16) float xlsT[FF][32];
    __shared__ __align__(16) float H2s[32][257];
    __shared__ float sp[8][32];

    const int n    = blockIdx.y;
    const int bblk = blockIdx.x;
    const int tid  = threadIdx.x;
    const int offs[5] = {0, -10, 1, 10, -1};

    for (int idx = tid; idx < FF * 32; idx += 256) {
        int f = idx / 32, b = idx % 32;
        int o = f / SS, sx = f % SS;
        int n2 = n + offs[o];
        float v = 0.0f;
        if (n2 >= 0 && n2 < NN) {
            size_t gb = (size_t)(bblk * 32 + b);
            v = x[(gb * TT + (TT - 1)) * (NN * SS) + n2 * SS + sx];
        }
        xlsT[f][b] = v;
    }
    __syncthreads();

    // layer 1: 8h x 8b f32x2 tile
    {
        const float* W1g = W1 + (size_t)n * FF * 512;
        const float* b1g = b1 + (size_t)n * 512;
        const int bg = tid >> 6;
        const int hg = tid & 63;
        ull acc[8][4];
        #pragma unroll
        for (int h = 0; h < 8; h++)
            #pragma unroll
            for (int p = 0; p < 4; p++) acc[h][p] = 0ULL;
        #pragma unroll 5
        for (int f = 0; f < FF; f++) {
            const float4* wv = reinterpret_cast<const float4*>(W1g + f * 512 + hg * 8);
            float4 wa = wv[0], wb = wv[1];
            ull wdp[8] = {dup2(wa.x), dup2(wa.y), dup2(wa.z), dup2(wa.w),
                          dup2(wb.x), dup2(wb.y), dup2(wb.z), dup2(wb.w)};
            const ull* xp = reinterpret_cast<const ull*>(&xlsT[f][bg * 8]);
            ull x0 = xp[0], x1 = xp[1], x2 = xp[2], x3 = xp[3];
            #pragma unroll
            for (int h = 0; h < 8; h++) {
                acc[h][0] = fma2(x0, wdp[h], acc[h][0]);
                acc[h][1] = fma2(x1, wdp[h], acc[h][1]);
                acc[h][2] = fma2(x2, wdp[h], acc[h][2]);
                acc[h][3] = fma2(x3, wdp[h], acc[h][3]);
            }
        }
        #pragma unroll
        for (int h = 0; h < 8; h++) {
            float bias = b1g[hg * 8 + h];
            float* row = &H1T[(hg * 8 + h) * FP + bg * 8];
            float4 v0, v1;
            v0.x = fmaxf(plo(acc[h][0]) + bias, 0.0f);
            v0.y = fmaxf(phi(acc[h][0]) + bias, 0.0f);
            v0.z = fmaxf(plo(acc[h][1]) + bias, 0.0f);
            v0.w = fmaxf(phi(acc[h][1]) + bias, 0.0f);
            v1.x = fmaxf(plo(acc[h][2]) + bias, 0.0f);
            v1.y = fmaxf(phi(acc[h][2]) + bias, 0.0f);
            v1.z = fmaxf(plo(acc[h][3]) + bias, 0.0f);
            v1.w = fmaxf(phi(acc[h][3]) + bias, 0.0f);
            reinterpret_cast<float4*>(row)[0] = v0;
            reinterpret_cast<float4*>(row)[1] = v1;
        }
    }
    __syncthreads();

    // layer 2: 4h x 8b f32x2 tile
    {
        const float4* W2g = reinterpret_cast<const float4*>(W2 + (size_t)n * 512 * 256);
        const float*  b2g = b2 + (size_t)n * 256;
        const int hg = tid & 63;
        const int bg = tid >> 6;
        ull acc[16];
        #pragma unroll
        for (int i = 0; i < 16; i++) acc[i] = 0ULL;
        #pragma unroll 4
        for (int f = 0; f < 512; f++) {
            float4 wv = W2g[f * 64 + hg];
            ull wdp[4] = {dup2(wv.x), dup2(wv.y), dup2(wv.z), dup2(wv.w)};
            const ull* xp = reinterpret_cast<const ull*>(&H1T[f * FP + bg * 8]);
            ull x0 = xp[0], x1 = xp[1], x2 = xp[2], x3 = xp[3];
            #pragma unroll
            for (int hh = 0; hh < 4; hh++) {
                acc[hh*4+0] = fma2(x0, wdp[hh], acc[hh*4+0]);
                acc[hh*4+1] = fma2(x1, wdp[hh], acc[hh*4+1]);
                acc[hh*4+2] = fma2(x2, wdp[hh], acc[hh*4+2]);
                acc[hh*4+3] = fma2(x3, wdp[hh], acc[hh*4+3]);
            }
        }
        #pragma unroll
        for (int hh = 0; hh < 4; hh++) {
            float bias = b2g[hg * 4 + hh];
            #pragma unroll
            for (int pi = 0; pi < 4; pi++) {
                int b = bg * 8 + pi * 2;
                H2s[b    ][hg * 4 + hh] = fmaxf(plo(acc[hh*4+pi]) + bias, 0.0f);
                H2s[b + 1][hg * 4 + hh] = fmaxf(phi(acc[hh*4+pi]) + bias, 0.0f);
            }
        }
    }
    __syncthreads();

    // layer 3
    {
        const float* W3g = W3 + (size_t)n * 256;
        int b = tid & 31, seg = tid >> 5;
        float sacc = 0.0f;
        #pragma unroll
        for (int c = 0; c < 32; c++)
            sacc = fmaf(H2s[b][seg * 32 + c], W3g[seg * 32 + c], sacc);
        sp[seg][b] = sacc;
    }
    __syncthreads();
    if (tid < 32) {
        float tot = b3[n];
        #pragma unroll
        for (int seg = 0; seg < 8; seg++) tot += sp[seg][tid];
        out[n * BB + bblk * 32 + tid] = tot;
    }
}

// ============================================================================
extern "C" void kernel_launch(void* const* d_in, const int* in_sizes, int n_in,
                              void* d_out, int out_size) {
    const float* x      = (const float*)d_in[0];
    const float* lm_W1  = (const float*)d_in[1];
    const float* lm_b1  = (const float*)d_in[2];
    const float* lm_W2  = (const float*)d_in[3];
    const float* lm_b2  = (const float*)d_in[4];
    const float* lm_W3  = (const float*)d_in[5];
    const float* lm_b3  = (const float*)d_in[6];
    const float* gWih   = (const float*)d_in[7];
    const float* gWhh   = (const float*)d_in[8];
    const float* gbih   = (const float*)d_in[9];
    const float* gbhh   = (const float*)d_in[10];
    const float* scW1   = (const float*)d_in[11];
    const float* scb1   = (const float*)d_in[12];
    const float* scW2   = (const float*)d_in[13];
    const float* scb2   = (const float*)d_in[14];
    const float* scW3   = (const float*)d_in[15];
    const float* scb3   = (const float*)d_in[16];
    float* out = (float*)d_out;

    const int h1t_bytes = 512 * FP * 4;                 // 73728
    const int a_bytes   = (35*48 + 2*35*XROW) * 4;      // 43680
    cudaFuncSetAttribute(lm_mlp_kernel,
                         cudaFuncAttributeMaxDynamicSharedMemorySize, h1t_bytes);
    cudaFuncSetAttribute(gi_gemm_kernel,
                         cudaFuncAttributeMaxDynamicSharedMemorySize, a_bytes);

    // A: gi GEMM
    dim3 gridA(TT / ACH, NN), blockA(128);
    gi_gemm_kernel<<<gridA, blockA, a_bytes>>>(x, gWih);

    // B: lm MLP (writes out)
    dim3 gridB(4, NN), blockB(256);
    lm_mlp_kernel<<<gridB, blockB, h1t_bytes>>>(
        x, lm_W1, lm_b1, lm_W2, lm_b2, lm_W3, lm_b3, out);

    // C: recurrence (reads gi, adds to out)
    dim3 gridC(16, NN), blockC(128);
    gru_rec_kernel<<<gridC, blockC>>>(
        gWhh, gbih, gbhh,
        scW1, scb1, scW2, scb2, scW3, scb3, out);
}

// round 7
// speedup vs baseline: 1.3223x; 1.1676x over previous
#include <cuda_runtime.h>
#include <cuda_fp16.h>
#include <cstdint>

#define BB   128
#define TT   256
#define NN   100
#define SS   7
#define GG   16
#define FF   35
#define FP   36   // padded H1 row stride in lm kernel
#define GROW 64   // gi row length in halfs (48 used, padded+swizzled to 128B)

typedef unsigned long long ull;

// gi scratch: [n][t][b][GROW] fp16, rows swizzled by s(b) = ((b>>3)&7)*4 (half2 words)
__device__ __half g_gi[(size_t)NN * TT * BB * GROW];

__device__ __forceinline__ ull fma2(ull a, ull b, ull c) {
    ull d; asm("fma.rn.f32x2 %0, %1, %2, %3;" : "=l"(d) : "l"(a), "l"(b), "l"(c));
    return d;
}
__device__ __forceinline__ ull dup2(float w) {
    ull d; asm("mov.b64 %0, {%1, %1};" : "=l"(d) : "f"(w));
    return d;
}
__device__ __forceinline__ float plo(ull p) { return __int_as_float((int)(unsigned)p); }
__device__ __forceinline__ float phi(ull p) { return __int_as_float((int)(p >> 32)); }

__device__ __forceinline__ float sigf(float x) {
    return __fdividef(1.0f, 1.0f + __expf(-x));
}
__device__ __forceinline__ float tanhfast(float x) {
    return __fdividef(2.0f, 1.0f + __expf(-2.0f * x)) - 1.0f;
}

__device__ __forceinline__ void cpasync4(uint32_t saddr, const float* gptr, int vbytes) {
    asm volatile("cp.async.ca.shared.global [%0], [%1], 4, %2;"
                 :: "r"(saddr), "l"(gptr), "r"(vbytes));
}
__device__ __forceinline__ void cpcommit() {
    asm volatile("cp.async.commit_group;");
}
__device__ __forceinline__ void cpwait0() {
    asm volatile("cp.async.wait_group 0;");
}

// ============================================================================
// Kernel A: gi GEMM -> g_gi[n][t][b][GROW] fp16 via conflict-free smem swizzle.
// 128 threads = (jq = tid&7: 6 j's) x (bq = tid>>3: 8 batches).
// ============================================================================
#define ACH 16
#define XROW 132   // padded xs row (floats), 16B-aligned stride

__global__ void __launch_bounds__(128) gi_gemm_kernel(
    const float* __restrict__ x,
    const float* __restrict__ Wih)
{
    extern __shared__ __align__(16) float smraw[];
    float*   wd  = smraw;                    // [35][48], j consecutive
    float*   xs  = wd + 35 * 48;             // [2][35][XROW]
    __half2* osm = reinterpret_cast<__half2*>(xs + 2 * 35 * XROW); // [128][32]

    const int n   = blockIdx.y;
    const int t0  = blockIdx.x * ACH;
    const int tid = threadIdx.x;
    const int jq  = tid & 7;      // owns j = jq*6 .. jq*6+5  (jp = jq*3..+2)
    const int bq  = tid >> 3;     // owns b = bq*8 .. bq*8+7
    const int swz = (bq & 7) * 4; // swizzle for rows this thread writes (b>>3 == bq)

    // stage weights once: Wih[n][g][f] -> wd[f*48 + g]
    const float* Wg = Wih + (size_t)n * 48 * FF;
    for (int i = tid; i < 48 * FF; i += 128)
        wd[(i % FF) * 48 + (i / FF)] = Wg[i];

    // x staging: thread (s = tid%7, q = tid/7 in 0..15), 112 active
    const int offs[5] = {0, -10, 1, 10, -1};
    const int s  = tid % 7;
    const int q  = tid / 7;
    const bool active = (q < 16);
    int nofs[5]; int vbytes[5];
    #pragma unroll
    for (int o = 0; o < 5; o++) {
        int n2 = n + offs[o];
        bool v = (n2 >= 0) && (n2 < NN);
        nofs[o]   = (v ? n2 : 0) * SS + s;
        vbytes[o] = v ? 4 : 0;
    }
    uint32_t xs_base = (uint32_t)__cvta_generic_to_shared(xs);

    auto stage = [&](int buf, int t) {
        if (active) {
            #pragma unroll
            for (int o = 0; o < 5; o++) {
                int f = o * 7 + s;
                #pragma unroll
                for (int bc = 0; bc < 8; bc++) {
                    int b = bc * 16 + q;
                    const float* gp = x + (size_t)b * (TT * NN * SS)
                                        + (size_t)t * (NN * SS) + nofs[o];
                    uint32_t sa = xs_base + (uint32_t)((buf * 35 * XROW + f * XROW + b) * 4);
                    cpasync4(sa, gp, vbytes[o]);
                }
            }
        }
        cpcommit();
    };

    stage(0, t0);
    cpwait0();
    __syncthreads();

    for (int tt = 0; tt < ACH; tt++) {
        const int t   = t0 + tt;
        const int cur = tt & 1;

        if (tt < ACH - 1) stage(cur ^ 1, t + 1);

        const float* xc = xs + cur * 35 * XROW;
        ull acc[3][8];
        #pragma unroll
        for (int jp = 0; jp < 3; jp++)
            #pragma unroll
            for (int b = 0; b < 8; b++) acc[jp][b] = 0ULL;

        #pragma unroll 5
        for (int f = 0; f < FF; f++) {
            const float4* xp = reinterpret_cast<const float4*>(&xc[f * XROW + bq * 8]);
            float4 xa = xp[0], xb = xp[1];
            ull xd[8] = {dup2(xa.x), dup2(xa.y), dup2(xa.z), dup2(xa.w),
                         dup2(xb.x), dup2(xb.y), dup2(xb.z), dup2(xb.w)};
            const ull* wp = reinterpret_cast<const ull*>(&wd[f * 48 + jq * 6]);
            ull w0 = wp[0], w1 = wp[1], w2 = wp[2];
            #pragma unroll
            for (int b = 0; b < 8; b++) {
                acc[0][b] = fma2(xd[b], w0, acc[0][b]);
                acc[1][b] = fma2(xd[b], w1, acc[1][b]);
                acc[2][b] = fma2(xd[b], w2, acc[2][b]);
            }
        }

        // swizzled STS: row b (32 half2), word (jq*3+i) ^ swz — conflict-free
        #pragma unroll
        for (int ib = 0; ib < 8; ib++) {
            __half2* row = osm + (size_t)(bq * 8 + ib) * 32;
            row[(jq * 3 + 0) ^ swz] = __floats2half2_rn(plo(acc[0][ib]), phi(acc[0][ib]));
            row[(jq * 3 + 1) ^ swz] = __floats2half2_rn(plo(acc[1][ib]), phi(acc[1][ib]));
            row[(jq * 3 + 2) ^ swz] = __floats2half2_rn(plo(acc[2][ib]), phi(acc[2][ib]));
        }
        __syncthreads();

        // coalesced copy-out: 16KB tile as float4 (swizzle XOR preserves 16B blocks)
        {
            const float4* src = reinterpret_cast<const float4*>(osm);
            float4* dst = reinterpret_cast<float4*>(
                g_gi + (size_t)(n * TT + t) * BB * GROW);
            #pragma unroll
            for (int r = 0; r < 8; r++)
                dst[r * 128 + tid] = src[r * 128 + tid];
        }

        cpwait0();
        __syncthreads();
    }
}

// ============================================================================
// Kernel C: recurrence + sc MLP. grid (16 bblk of 8 batches, 100 n), 128 thr.
// Warp owns 2 batches; lane = (j in 16, bh in 2). Whh in regs, __syncwarp only.
// gi rows are swizzled with s = (bblk&7)*4 — offsets precomputed per thread.
// ============================================================================
__global__ void __launch_bounds__(128) gru_rec_kernel(
    const float* __restrict__ Whh,
    const float* __restrict__ bih, const float* __restrict__ bhh,
    const float* __restrict__ scW1, const float* __restrict__ scb1,
    const float* __restrict__ scW2, const float* __restrict__ scb2,
    const float* __restrict__ scW3, const float* __restrict__ scb3,
    float* __restrict__ out)
{
    __shared__ __align__(16) float shf[4][2][2][16];  // [warp][buf][bh][k]

    const int n    = blockIdx.y;
    const int bblk = blockIdx.x;
    const int tid  = threadIdx.x;
    const int w    = tid >> 5;
    const int lane = tid & 31;
    const int j    = lane & 15;
    const int bh   = lane >> 4;
    const int bglob = bblk * 8 + w * 2 + bh;   // b>>3 == bblk

    const ull* wrp = reinterpret_cast<const ull*>(Whh + ((size_t)n * 48 + j     ) * GG);
    const ull* wzp = reinterpret_cast<const ull*>(Whh + ((size_t)n * 48 + j + 16) * GG);
    const ull* wnp = reinterpret_cast<const ull*>(Whh + ((size_t)n * 48 + j + 32) * GG);
    ull wr[8], wz[8], wn[8];
    #pragma unroll
    for (int k = 0; k < 8; k++) { wr[k] = wrp[k]; wz[k] = wzp[k]; wn[k] = wnp[k]; }

    const float br  = bih[n * 48 + j     ] + bhh[n * 48 + j     ];
    const float bz  = bih[n * 48 + j + 16] + bhh[n * 48 + j + 16];
    const float bin = bih[n * 48 + j + 32];
    const float bhn = bhh[n * 48 + j + 32];

    // swizzled in-row half offsets
    const int sw  = (bblk & 7) * 4;
    const int o_r = (((j      ) >> 1) ^ sw) * 2 + (j & 1);
    const int o_z = (((j + 16 ) >> 1) ^ sw) * 2 + (j & 1);
    const int o_n = (((j + 32 ) >> 1) ^ sw) * 2 + (j & 1);

    shf[w][0][bh][j] = 0.0f;
    float hreg = 0.0f;
    __syncwarp();

    const __half* gbase = g_gi + ((size_t)n * TT * BB + bglob) * GROW;
    float gir = __half2float(gbase[o_r]);
    float giz = __half2float(gbase[o_z]);
    float gin = __half2float(gbase[o_n]);

    int cur = 0;
    for (int t = 0; t < TT; t++) {
        const __half* grn = gbase + (size_t)((t + 1 < TT) ? t + 1 : t) * BB * GROW;
        float pgr = __half2float(grn[o_r]);
        float pgz = __half2float(grn[o_z]);
        float pgn = __half2float(grn[o_n]);

        const ull* hp = reinterpret_cast<const ull*>(&shf[w][cur][bh][0]);
        ull ar = 0ULL, az = 0ULL, an = 0ULL;
        #pragma unroll
        for (int k = 0; k < 8; k++) {
            ull hk = hp[k];
            ar = fma2(hk, wr[k], ar);
            az = fma2(hk, wz[k], az);
            an = fma2(hk, wn[k], an);
        }
        float r  = sigf(br + gir + plo(ar) + phi(ar));
        float z  = sigf(bz + giz + plo(az) + phi(az));
        float nv = tanhfast(bin + gin + r * (bhn + plo(an) + phi(an)));
        float hnew = nv + z * (hreg - nv);
        hreg = hnew;
        shf[w][cur ^ 1][bh][j] = hnew;
        __syncwarp();
        gir = pgr; giz = pgz; gin = pgn;
        cur ^= 1;
    }

    // sc MLP epilogue
    shf[w][0][bh][j] = hreg;
    __syncwarp();
    {
        float a = scb1[n * GG + j];
        #pragma unroll
        for (int k = 0; k < GG; k++)
            a = fmaf(shf[w][0][bh][k], scW1[((size_t)n * GG + k) * GG + j], a);
        shf[w][1][bh][j] = fmaxf(a, 0.0f);
    }
    __syncwarp();
    {
        float a = scb2[n * GG + j];
        #pragma unroll
        for (int k = 0; k < GG; k++)
            a = fmaf(shf[w][1][bh][k], scW2[((size_t)n * GG + k) * GG + j], a);
        shf[w][0][bh][j] = fmaxf(a, 0.0f);
    }
    __syncwarp();
    if (j == 0) {
        float q = scb3[n];
        #pragma unroll
        for (int k = 0; k < GG; k++)
            q = fmaf(shf[w][0][bh][k], scW3[n * GG + k], q);
        int idx = n * BB + bglob;
        out[idx] = out[idx] + q;   // lm kernel already wrote f
    }
}

// ============================================================================
// Kernel B: lm MLP on xl = gather(x[:, T-1]) -> WRITES f into out[n*B + b]
// ============================================================================
__global__ void __launch_bounds__(256) lm_mlp_kernel(
    const float* __restrict__ x,
    const float* __restrict__ W1, const float* __restrict__ b1,
    const float* __restrict__ W2, const float* __restrict__ b2,
    const float* __restrict__ W3, const float* __restrict__ b3,
    float* __restrict__ out)
{
    extern __shared__ __align__(16) float H1T[];      // [512][36]
    __shared__ __align__(16) float xlsT[FF][32];
    __shared__ __align__(16) float H2s[32][257];
    __shared__ float sp[8][32];

    const int n    = blockIdx.y;
    const int bblk = blockIdx.x;
    const int tid  = threadIdx.x;
    const int offs[5] = {0, -10, 1, 10, -1};

    for (int idx = tid; idx < FF * 32; idx += 256) {
        int f = idx / 32, b = idx % 32;
        int o = f / SS, sx = f % SS;
        int n2 = n + offs[o];
        float v = 0.0f;
        if (n2 >= 0 && n2 < NN) {
            size_t gb = (size_t)(bblk * 32 + b);
            v = x[(gb * TT + (TT - 1)) * (NN * SS) + n2 * SS + sx];
        }
        xlsT[f][b] = v;
    }
    __syncthreads();

    // layer 1: 8h x 8b f32x2 tile
    {
        const float* W1g = W1 + (size_t)n * FF * 512;
        const float* b1g = b1 + (size_t)n * 512;
        const int bg = tid >> 6;
        const int hg = tid & 63;
        ull acc[8][4];
        #pragma unroll
        for (int h = 0; h < 8; h++)
            #pragma unroll
            for (int p = 0; p < 4; p++) acc[h][p] = 0ULL;
        #pragma unroll 5
        for (int f = 0; f < FF; f++) {
            const float4* wv = reinterpret_cast<const float4*>(W1g + f * 512 + hg * 8);
            float4 wa = wv[0], wb = wv[1];
            ull wdp[8] = {dup2(wa.x), dup2(wa.y), dup2(wa.z), dup2(wa.w),
                          dup2(wb.x), dup2(wb.y), dup2(wb.z), dup2(wb.w)};
            const ull* xp = reinterpret_cast<const ull*>(&xlsT[f][bg * 8]);
            ull x0 = xp[0], x1 = xp[1], x2 = xp[2], x3 = xp[3];
            #pragma unroll
            for (int h = 0; h < 8; h++) {
                acc[h][0] = fma2(x0, wdp[h], acc[h][0]);
                acc[h][1] = fma2(x1, wdp[h], acc[h][1]);
                acc[h][2] = fma2(x2, wdp[h], acc[h][2]);
                acc[h][3] = fma2(x3, wdp[h], acc[h][3]);
            }
        }
        #pragma unroll
        for (int h = 0; h < 8; h++) {
            float bias = b1g[hg * 8 + h];
            float* row = &H1T[(hg * 8 + h) * FP + bg * 8];
            float4 v0, v1;
            v0.x = fmaxf(plo(acc[h][0]) + bias, 0.0f);
            v0.y = fmaxf(phi(acc[h][0]) + bias, 0.0f);
            v0.z = fmaxf(plo(acc[h][1]) + bias, 0.0f);
            v0.w = fmaxf(phi(acc[h][1]) + bias, 0.0f);
            v1.x = fmaxf(plo(acc[h][2]) + bias, 0.0f);
            v1.y = fmaxf(phi(acc[h][2]) + bias, 0.0f);
            v1.z = fmaxf(plo(acc[h][3]) + bias, 0.0f);
            v1.w = fmaxf(phi(acc[h][3]) + bias, 0.0f);
            reinterpret_cast<float4*>(row)[0] = v0;
            reinterpret_cast<float4*>(row)[1] = v1;
        }
    }
    __syncthreads();

    // layer 2: 4h x 8b f32x2 tile
    {
        const float4* W2g = reinterpret_cast<const float4*>(W2 + (size_t)n * 512 * 256);
        const float*  b2g = b2 + (size_t)n * 256;
        const int hg = tid & 63;
        const int bg = tid >> 6;
        ull acc[16];
        #pragma unroll
        for (int i = 0; i < 16; i++) acc[i] = 0ULL;
        #pragma unroll 4
        for (int f = 0; f < 512; f++) {
            float4 wv = W2g[f * 64 + hg];
            ull wdp[4] = {dup2(wv.x), dup2(wv.y), dup2(wv.z), dup2(wv.w)};
            const ull* xp = reinterpret_cast<const ull*>(&H1T[f * FP + bg * 8]);
            ull x0 = xp[0], x1 = xp[1], x2 = xp[2], x3 = xp[3];
            #pragma unroll
            for (int hh = 0; hh < 4; hh++) {
                acc[hh*4+0] = fma2(x0, wdp[hh], acc[hh*4+0]);
                acc[hh*4+1] = fma2(x1, wdp[hh], acc[hh*4+1]);
                acc[hh*4+2] = fma2(x2, wdp[hh], acc[hh*4+2]);
                acc[hh*4+3] = fma2(x3, wdp[hh], acc[hh*4+3]);
            }
        }
        #pragma unroll
        for (int hh = 0; hh < 4; hh++) {
            float bias = b2g[hg * 4 + hh];
            #pragma unroll
            for (int pi = 0; pi < 4; pi++) {
                int b = bg * 8 + pi * 2;
                H2s[b    ][hg * 4 + hh] = fmaxf(plo(acc[hh*4+pi]) + bias, 0.0f);
                H2s[b + 1][hg * 4 + hh] = fmaxf(phi(acc[hh*4+pi]) + bias, 0.0f);
            }
        }
    }
    __syncthreads();

    // layer 3
    {
        const float* W3g = W3 + (size_t)n * 256;
        int b = tid & 31, seg = tid >> 5;
        float sacc = 0.0f;
        #pragma unroll
        for (int c = 0; c < 32; c++)
            sacc = fmaf(H2s[b][seg * 32 + c], W3g[seg * 32 + c], sacc);
        sp[seg][b] = sacc;
    }
    __syncthreads();
    if (tid < 32) {
        float tot = b3[n];
        #pragma unroll
        for (int seg = 0; seg < 8; seg++) tot += sp[seg][tid];
        out[n * BB + bblk * 32 + tid] = tot;
    }
}

// ============================================================================
extern "C" void kernel_launch(void* const* d_in, const int* in_sizes, int n_in,
                              void* d_out, int out_size) {
    const float* x      = (const float*)d_in[0];
    const float* lm_W1  = (const float*)d_in[1];
    const float* lm_b1  = (const float*)d_in[2];
    const float* lm_W2  = (const float*)d_in[3];
    const float* lm_b2  = (const float*)d_in[4];
    const float* lm_W3  = (const float*)d_in[5];
    const float* lm_b3  = (const float*)d_in[6];
    const float* gWih   = (const float*)d_in[7];
    const float* gWhh   = (const float*)d_in[8];
    const float* gbih   = (const float*)d_in[9];
    const float* gbhh   = (const float*)d_in[10];
    const float* scW1   = (const float*)d_in[11];
    const float* scb1   = (const float*)d_in[12];
    const float* scW2   = (const float*)d_in[13];
    const float* scb2   = (const float*)d_in[14];
    const float* scW3   = (const float*)d_in[15];
    const float* scb3   = (const float*)d_in[16];
    float* out = (float*)d_out;

    const int h1t_bytes = 512 * FP * 4;                              // 73728
    const int a_bytes   = (35*48 + 2*35*XROW) * 4 + 128 * 32 * 4;    // 60064
    cudaFuncSetAttribute(lm_mlp_kernel,
                         cudaFuncAttributeMaxDynamicSharedMemorySize, h1t_bytes);
    cudaFuncSetAttribute(gi_gemm_kernel,
                         cudaFuncAttributeMaxDynamicSharedMemorySize, a_bytes);

    // A: gi GEMM
    dim3 gridA(TT / ACH, NN), blockA(128);
    gi_gemm_kernel<<<gridA, blockA, a_bytes>>>(x, gWih);

    // B: lm MLP (writes out)
    dim3 gridB(4, NN), blockB(256);
    lm_mlp_kernel<<<gridB, blockB, h1t_bytes>>>(
        x, lm_W1, lm_b1, lm_W2, lm_b2, lm_W3, lm_b3, out);

    // C: recurrence (reads gi, adds to out)
    dim3 gridC(16, NN), blockC(128);
    gru_rec_kernel<<<gridC, blockC>>>(
        gWhh, gbih, gbhh,
        scW1, scb1, scW2, scb2, scW3, scb3, out);
}

// round 8
// speedup vs baseline: 1.3881x; 1.0497x over previous
#include <cuda_runtime.h>
#include <cuda_fp16.h>
#include <cstdint>

#define BB   128
#define TT   256
#define NN   100
#define SS   7
#define GG   16
#define FF   35
#define FP   36   // padded H1 row stride in lm role
#define GROW 64   // gi row length in halfs (48 used, padded+swizzled to 128B)

typedef unsigned long long ull;

// gi scratch: [n][t][b][GROW] fp16, rows swizzled by s(b) = ((b>>3)&7)*4 (half2 words)
__device__ __half g_gi[(size_t)NN * TT * BB * GROW];

__device__ __forceinline__ ull fma2(ull a, ull b, ull c) {
    ull d; asm("fma.rn.f32x2 %0, %1, %2, %3;" : "=l"(d) : "l"(a), "l"(b), "l"(c));
    return d;
}
__device__ __forceinline__ ull dup2(float w) {
    ull d; asm("mov.b64 %0, {%1, %1};" : "=l"(d) : "f"(w));
    return d;
}
__device__ __forceinline__ float plo(ull p) { return __int_as_float((int)(unsigned)p); }
__device__ __forceinline__ float phi(ull p) { return __int_as_float((int)(p >> 32)); }

__device__ __forceinline__ float sigf(float x) {
    return __fdividef(1.0f, 1.0f + __expf(-x));
}
__device__ __forceinline__ float tanhfast(float x) {
    return __fdividef(2.0f, 1.0f + __expf(-2.0f * x)) - 1.0f;
}

__device__ __forceinline__ void cpasync4(uint32_t saddr, const float* gptr, int vbytes) {
    asm volatile("cp.async.ca.shared.global [%0], [%1], 4, %2;"
                 :: "r"(saddr), "l"(gptr), "r"(vbytes));
}
__device__ __forceinline__ void cpcommit() {
    asm volatile("cp.async.commit_group;");
}
__device__ __forceinline__ void cpwait0() {
    asm volatile("cp.async.wait_group 0;");
}

// ============================================================================
// Kernel A: gi GEMM -> g_gi[n][t][b][GROW] fp16 via conflict-free smem swizzle.
// Also zeroes out[] (block x==0) so the fused BC kernel can atomicAdd.
// ============================================================================
#define ACH 16
#define XROW 132   // padded xs row (floats), 16B-aligned stride

__global__ void __launch_bounds__(128) gi_gemm_kernel(
    const float* __restrict__ x,
    const float* __restrict__ Wih,
    float* __restrict__ out)
{
    extern __shared__ __align__(16) float smraw[];
    float*   wd  = smraw;                    // [35][48], j consecutive
    float*   xs  = wd + 35 * 48;             // [2][35][XROW]
    __half2* osm = reinterpret_cast<__half2*>(xs + 2 * 35 * XROW); // [128][32]

    const int n   = blockIdx.y;
    const int t0  = blockIdx.x * ACH;
    const int tid = threadIdx.x;
    const int jq  = tid & 7;      // owns j = jq*6 .. jq*6+5
    const int bq  = tid >> 3;     // owns b = bq*8 .. bq*8+7
    const int swz = (bq & 7) * 4;

    // zero out[] for the fused BC kernel's atomic adds
    if (blockIdx.x == 0) out[n * BB + tid] = 0.0f;

    // stage weights once: Wih[n][g][f] -> wd[f*48 + g]
    const float* Wg = Wih + (size_t)n * 48 * FF;
    for (int i = tid; i < 48 * FF; i += 128)
        wd[(i % FF) * 48 + (i / FF)] = Wg[i];

    // x staging: thread (s = tid%7, q = tid/7 in 0..15), 112 active
    const int offs[5] = {0, -10, 1, 10, -1};
    const int s  = tid % 7;
    const int q  = tid / 7;
    const bool active = (q < 16);
    int nofs[5]; int vbytes[5];
    #pragma unroll
    for (int o = 0; o < 5; o++) {
        int n2 = n + offs[o];
        bool v = (n2 >= 0) && (n2 < NN);
        nofs[o]   = (v ? n2 : 0) * SS + s;
        vbytes[o] = v ? 4 : 0;
    }
    uint32_t xs_base = (uint32_t)__cvta_generic_to_shared(xs);

    auto stage = [&](int buf, int t) {
        if (active) {
            #pragma unroll
            for (int o = 0; o < 5; o++) {
                int f = o * 7 + s;
                #pragma unroll
                for (int bc = 0; bc < 8; bc++) {
                    int b = bc * 16 + q;
                    const float* gp = x + (size_t)b * (TT * NN * SS)
                                        + (size_t)t * (NN * SS) + nofs[o];
                    uint32_t sa = xs_base + (uint32_t)((buf * 35 * XROW + f * XROW + b) * 4);
                    cpasync4(sa, gp, vbytes[o]);
                }
            }
        }
        cpcommit();
    };

    stage(0, t0);
    cpwait0();
    __syncthreads();

    for (int tt = 0; tt < ACH; tt++) {
        const int t   = t0 + tt;
        const int cur = tt & 1;

        if (tt < ACH - 1) stage(cur ^ 1, t + 1);

        const float* xc = xs + cur * 35 * XROW;
        ull acc[3][8];
        #pragma unroll
        for (int jp = 0; jp < 3; jp++)
            #pragma unroll
            for (int b = 0; b < 8; b++) acc[jp][b] = 0ULL;

        #pragma unroll 5
        for (int f = 0; f < FF; f++) {
            const float4* xp = reinterpret_cast<const float4*>(&xc[f * XROW + bq * 8]);
            float4 xa = xp[0], xb = xp[1];
            ull xd[8] = {dup2(xa.x), dup2(xa.y), dup2(xa.z), dup2(xa.w),
                         dup2(xb.x), dup2(xb.y), dup2(xb.z), dup2(xb.w)};
            const ull* wp = reinterpret_cast<const ull*>(&wd[f * 48 + jq * 6]);
            ull w0 = wp[0], w1 = wp[1], w2 = wp[2];
            #pragma unroll
            for (int b = 0; b < 8; b++) {
                acc[0][b] = fma2(xd[b], w0, acc[0][b]);
                acc[1][b] = fma2(xd[b], w1, acc[1][b]);
                acc[2][b] = fma2(xd[b], w2, acc[2][b]);
            }
        }

        // swizzled STS: row b (32 half2), word (jq*3+i) ^ swz — conflict-free
        #pragma unroll
        for (int ib = 0; ib < 8; ib++) {
            __half2* row = osm + (size_t)(bq * 8 + ib) * 32;
            row[(jq * 3 + 0) ^ swz] = __floats2half2_rn(plo(acc[0][ib]), phi(acc[0][ib]));
            row[(jq * 3 + 1) ^ swz] = __floats2half2_rn(plo(acc[1][ib]), phi(acc[1][ib]));
            row[(jq * 3 + 2) ^ swz] = __floats2half2_rn(plo(acc[2][ib]), phi(acc[2][ib]));
        }
        __syncthreads();

        // coalesced copy-out
        {
            const float4* src = reinterpret_cast<const float4*>(osm);
            float4* dst = reinterpret_cast<float4*>(
                g_gi + (size_t)(n * TT + t) * BB * GROW);
            #pragma unroll
            for (int r = 0; r < 8; r++)
                dst[r * 128 + tid] = src[r * 128 + tid];
        }

        cpwait0();
        __syncthreads();
    }
}

// ============================================================================
// Fused kernel BC: 1200 blocks x 256 threads, role by bid % 3.
//   role B (bid%3==0, 400 blocks): lm MLP, atomicAdd f into out.
//   role C (else, 800 blocks): GRU recurrence for 16 batches (8 warps),
//     warp-local (__syncwarp only), atomicAdd q into out.
// Dynamic smem: B uses it as H1T[512][36]; C uses first 4KB as h-exchange.
// ============================================================================
__global__ void __launch_bounds__(256) bc_fused_kernel(
    const float* __restrict__ x,
    const float* __restrict__ W1, const float* __restrict__ b1,
    const float* __restrict__ W2, const float* __restrict__ b2,
    const float* __restrict__ W3, const float* __restrict__ b3,
    const float* __restrict__ Whh,
    const float* __restrict__ bih, const float* __restrict__ bhh,
    const float* __restrict__ scW1, const float* __restrict__ scb1,
    const float* __restrict__ scW2, const float* __restrict__ scb2,
    const float* __restrict__ scW3, const float* __restrict__ scb3,
    float* __restrict__ out)
{
    extern __shared__ __align__(16) float dyn[];   // B: H1T[512][36]; C: shf
    __shared__ __align__(16) float xlsT[FF][32];
    __shared__ __align__(16) float H2s[32][257];
    __shared__ float sp[8][32];

    const int bid = blockIdx.x;
    const int tid = threadIdx.x;

    if (bid % 3 == 0) {
        // ==================== role B: lm MLP ====================
        const int bidx = bid / 3;          // 0..399
        const int n    = bidx >> 2;
        const int bblk = bidx & 3;
        float* H1T = dyn;
        const int offs[5] = {0, -10, 1, 10, -1};

        for (int idx = tid; idx < FF * 32; idx += 256) {
            int f = idx / 32, b = idx % 32;
            int o = f / SS, sx = f % SS;
            int n2 = n + offs[o];
            float v = 0.0f;
            if (n2 >= 0 && n2 < NN) {
                size_t gb = (size_t)(bblk * 32 + b);
                v = x[(gb * TT + (TT - 1)) * (NN * SS) + n2 * SS + sx];
            }
            xlsT[f][b] = v;
        }
        __syncthreads();

        // layer 1: 8h x 8b f32x2 tile
        {
            const float* W1g = W1 + (size_t)n * FF * 512;
            const float* b1g = b1 + (size_t)n * 512;
            const int bg = tid >> 6;
            const int hg = tid & 63;
            ull acc[8][4];
            #pragma unroll
            for (int h = 0; h < 8; h++)
                #pragma unroll
                for (int p = 0; p < 4; p++) acc[h][p] = 0ULL;
            #pragma unroll 5
            for (int f = 0; f < FF; f++) {
                const float4* wv = reinterpret_cast<const float4*>(W1g + f * 512 + hg * 8);
                float4 wa = wv[0], wb = wv[1];
                ull wdp[8] = {dup2(wa.x), dup2(wa.y), dup2(wa.z), dup2(wa.w),
                              dup2(wb.x), dup2(wb.y), dup2(wb.z), dup2(wb.w)};
                const ull* xp = reinterpret_cast<const ull*>(&xlsT[f][bg * 8]);
                ull x0 = xp[0], x1 = xp[1], x2 = xp[2], x3 = xp[3];
                #pragma unroll
                for (int h = 0; h < 8; h++) {
                    acc[h][0] = fma2(x0, wdp[h], acc[h][0]);
                    acc[h][1] = fma2(x1, wdp[h], acc[h][1]);
                    acc[h][2] = fma2(x2, wdp[h], acc[h][2]);
                    acc[h][3] = fma2(x3, wdp[h], acc[h][3]);
                }
            }
            #pragma unroll
            for (int h = 0; h < 8; h++) {
                float bias = b1g[hg * 8 + h];
                float* row = &H1T[(hg * 8 + h) * FP + bg * 8];
                float4 v0, v1;
                v0.x = fmaxf(plo(acc[h][0]) + bias, 0.0f);
                v0.y = fmaxf(phi(acc[h][0]) + bias, 0.0f);
                v0.z = fmaxf(plo(acc[h][1]) + bias, 0.0f);
                v0.w = fmaxf(phi(acc[h][1]) + bias, 0.0f);
                v1.x = fmaxf(plo(acc[h][2]) + bias, 0.0f);
                v1.y = fmaxf(phi(acc[h][2]) + bias, 0.0f);
                v1.z = fmaxf(plo(acc[h][3]) + bias, 0.0f);
                v1.w = fmaxf(phi(acc[h][3]) + bias, 0.0f);
                reinterpret_cast<float4*>(row)[0] = v0;
                reinterpret_cast<float4*>(row)[1] = v1;
            }
        }
        __syncthreads();

        // layer 2: 4h x 8b f32x2 tile
        {
            const float4* W2g = reinterpret_cast<const float4*>(W2 + (size_t)n * 512 * 256);
            const float*  b2g = b2 + (size_t)n * 256;
            const int hg = tid & 63;
            const int bg = tid >> 6;
            ull acc[16];
            #pragma unroll
            for (int i = 0; i < 16; i++) acc[i] = 0ULL;
            #pragma unroll 4
            for (int f = 0; f < 512; f++) {
                float4 wv = W2g[f * 64 + hg];
                ull wdp[4] = {dup2(wv.x), dup2(wv.y), dup2(wv.z), dup2(wv.w)};
                const ull* xp = reinterpret_cast<const ull*>(&H1T[f * FP + bg * 8]);
                ull x0 = xp[0], x1 = xp[1], x2 = xp[2], x3 = xp[3];
                #pragma unroll
                for (int hh = 0; hh < 4; hh++) {
                    acc[hh*4+0] = fma2(x0, wdp[hh], acc[hh*4+0]);
                    acc[hh*4+1] = fma2(x1, wdp[hh], acc[hh*4+1]);
                    acc[hh*4+2] = fma2(x2, wdp[hh], acc[hh*4+2]);
                    acc[hh*4+3] = fma2(x3, wdp[hh], acc[hh*4+3]);
                }
            }
            #pragma unroll
            for (int hh = 0; hh < 4; hh++) {
                float bias = b2g[hg * 4 + hh];
                #pragma unroll
                for (int pi = 0; pi < 4; pi++) {
                    int b = bg * 8 + pi * 2;
                    H2s[b    ][hg * 4 + hh] = fmaxf(plo(acc[hh*4+pi]) + bias, 0.0f);
                    H2s[b + 1][hg * 4 + hh] = fmaxf(phi(acc[hh*4+pi]) + bias, 0.0f);
                }
            }
        }
        __syncthreads();

        // layer 3
        {
            const float* W3g = W3 + (size_t)n * 256;
            int b = tid & 31, seg = tid >> 5;
            float sacc = 0.0f;
            #pragma unroll
            for (int c = 0; c < 32; c++)
                sacc = fmaf(H2s[b][seg * 32 + c], W3g[seg * 32 + c], sacc);
            sp[seg][b] = sacc;
        }
        __syncthreads();
        if (tid < 32) {
            float tot = b3[n];
            #pragma unroll
            for (int seg = 0; seg < 8; seg++) tot += sp[seg][tid];
            atomicAdd(&out[n * BB + bblk * 32 + tid], tot);
        }
    } else {
        // ==================== role C: GRU recurrence ====================
        const int cidx = bid - (bid / 3 + 1);   // 0..799
        const int n     = cidx >> 3;
        const int bbase = (cidx & 7) * 16;

        float (*shf)[2][2][16] = reinterpret_cast<float(*)[2][2][16]>(dyn); // [8 warps]

        const int w    = tid >> 5;
        const int lane = tid & 31;
        const int j    = lane & 15;
        const int bh   = lane >> 4;
        const int bglob = bbase + w * 2 + bh;

        const ull* wrp = reinterpret_cast<const ull*>(Whh + ((size_t)n * 48 + j     ) * GG);
        const ull* wzp = reinterpret_cast<const ull*>(Whh + ((size_t)n * 48 + j + 16) * GG);
        const ull* wnp = reinterpret_cast<const ull*>(Whh + ((size_t)n * 48 + j + 32) * GG);
        ull wr[8], wz[8], wn[8];
        #pragma unroll
        for (int k = 0; k < 8; k++) { wr[k] = wrp[k]; wz[k] = wzp[k]; wn[k] = wnp[k]; }

        const float br  = bih[n * 48 + j     ] + bhh[n * 48 + j     ];
        const float bz  = bih[n * 48 + j + 16] + bhh[n * 48 + j + 16];
        const float bin = bih[n * 48 + j + 32];
        const float bhn = bhh[n * 48 + j + 32];

        // swizzled in-row half offsets (gi row swizzle keyed by b>>3)
        const int sw  = ((bglob >> 3) & 7) * 4;
        const int o_r = (((j      ) >> 1) ^ sw) * 2 + (j & 1);
        const int o_z = (((j + 16 ) >> 1) ^ sw) * 2 + (j & 1);
        const int o_n = (((j + 32 ) >> 1) ^ sw) * 2 + (j & 1);

        shf[w][0][bh][j] = 0.0f;
        float hreg = 0.0f;
        __syncwarp();

        const __half* gbase = g_gi + ((size_t)n * TT * BB + bglob) * GROW;
        float gir = __half2float(gbase[o_r]);
        float giz = __half2float(gbase[o_z]);
        float gin = __half2float(gbase[o_n]);

        int cur = 0;
        for (int t = 0; t < TT; t++) {
            const __half* grn = gbase + (size_t)((t + 1 < TT) ? t + 1 : t) * BB * GROW;
            float pgr = __half2float(grn[o_r]);
            float pgz = __half2float(grn[o_z]);
            float pgn = __half2float(grn[o_n]);

            const ull* hp = reinterpret_cast<const ull*>(&shf[w][cur][bh][0]);
            ull ar = 0ULL, az = 0ULL, an = 0ULL;
            #pragma unroll
            for (int k = 0; k < 8; k++) {
                ull hk = hp[k];
                ar = fma2(hk, wr[k], ar);
                az = fma2(hk, wz[k], az);
                an = fma2(hk, wn[k], an);
            }
            float r  = sigf(br + gir + plo(ar) + phi(ar));
            float z  = sigf(bz + giz + plo(az) + phi(az));
            float nv = tanhfast(bin + gin + r * (bhn + plo(an) + phi(an)));
            float hnew = nv + z * (hreg - nv);
            hreg = hnew;
            shf[w][cur ^ 1][bh][j] = hnew;
            __syncwarp();
            gir = pgr; giz = pgz; gin = pgn;
            cur ^= 1;
        }

        // sc MLP epilogue
        shf[w][0][bh][j] = hreg;
        __syncwarp();
        {
            float a = scb1[n * GG + j];
            #pragma unroll
            for (int k = 0; k < GG; k++)
                a = fmaf(shf[w][0][bh][k], scW1[((size_t)n * GG + k) * GG + j], a);
            shf[w][1][bh][j] = fmaxf(a, 0.0f);
        }
        __syncwarp();
        {
            float a = scb2[n * GG + j];
            #pragma unroll
            for (int k = 0; k < GG; k++)
                a = fmaf(shf[w][1][bh][k], scW2[((size_t)n * GG + k) * GG + j], a);
            shf[w][0][bh][j] = fmaxf(a, 0.0f);
        }
        __syncwarp();
        if (j == 0) {
            float q = scb3[n];
            #pragma unroll
            for (int k = 0; k < GG; k++)
                q = fmaf(shf[w][0][bh][k], scW3[n * GG + k], q);
            atomicAdd(&out[n * BB + bglob], q);
        }
    }
}

// ============================================================================
extern "C" void kernel_launch(void* const* d_in, const int* in_sizes, int n_in,
                              void* d_out, int out_size) {
    const float* x      = (const float*)d_in[0];
    const float* lm_W1  = (const float*)d_in[1];
    const float* lm_b1  = (const float*)d_in[2];
    const float* lm_W2  = (const float*)d_in[3];
    const float* lm_b2  = (const float*)d_in[4];
    const float* lm_W3  = (const float*)d_in[5];
    const float* lm_b3  = (const float*)d_in[6];
    const float* gWih   = (const float*)d_in[7];
    const float* gWhh   = (const float*)d_in[8];
    const float* gbih   = (const float*)d_in[9];
    const float* gbhh   = (const float*)d_in[10];
    const float* scW1   = (const float*)d_in[11];
    const float* scb1   = (const float*)d_in[12];
    const float* scW2   = (const float*)d_in[13];
    const float* scb2   = (const float*)d_in[14];
    const float* scW3   = (const float*)d_in[15];
    const float* scb3   = (const float*)d_in[16];
    float* out = (float*)d_out;

    const int bc_bytes = 512 * FP * 4;                               // 73728
    const int a_bytes  = (35*48 + 2*35*XROW) * 4 + 128 * 32 * 4;     // 60064
    cudaFuncSetAttribute(bc_fused_kernel,
                         cudaFuncAttributeMaxDynamicSharedMemorySize, bc_bytes);
    cudaFuncSetAttribute(gi_gemm_kernel,
                         cudaFuncAttributeMaxDynamicSharedMemorySize, a_bytes);

    // A: gi GEMM (+ zero out)
    dim3 gridA(TT / ACH, NN), blockA(128);
    gi_gemm_kernel<<<gridA, blockA, a_bytes>>>(x, gWih, out);

    // BC fused: lm MLP + GRU recurrence, co-scheduled
    bc_fused_kernel<<<1200, 256, bc_bytes>>>(
        x, lm_W1, lm_b1, lm_W2, lm_b2, lm_W3, lm_b3,
        gWhh, gbih, gbhh,
        scW1, scb1, scW2, scb2, scW3, scb3, out);
}

// round 9
// speedup vs baseline: 1.5125x; 1.0896x over previous
#include <cuda_runtime.h>
#include <cuda_fp16.h>
#include <cstdint>

#define BB   128
#define TT   256
#define NN   100
#define SS   7
#define GG   16
#define FF   35
#define GROW 64   // gi row length in halfs (48 used, padded+swizzled to 128B)
#define H1ROW 520 // H1T row stride (floats): 512 + 8 pad

typedef unsigned long long ull;

// gi scratch: [n][t][b][GROW] fp16, rows swizzled by s(b) = ((b>>3)&7)*4 (half2 words)
__device__ __half g_gi[(size_t)NN * TT * BB * GROW];

__device__ __forceinline__ ull fma2(ull a, ull b, ull c) {
    ull d; asm("fma.rn.f32x2 %0, %1, %2, %3;" : "=l"(d) : "l"(a), "l"(b), "l"(c));
    return d;
}
__device__ __forceinline__ ull dup2(float w) {
    ull d; asm("mov.b64 %0, {%1, %1};" : "=l"(d) : "f"(w));
    return d;
}
__device__ __forceinline__ float plo(ull p) { return __int_as_float((int)(unsigned)p); }
__device__ __forceinline__ float phi(ull p) { return __int_as_float((int)(p >> 32)); }

__device__ __forceinline__ float tanhhw(float x) {
    float y; asm("tanh.approx.f32 %0, %1;" : "=f"(y) : "f"(x));
    return y;
}
__device__ __forceinline__ float sighw(float x) {
    return 0.5f * tanhhw(0.5f * x) + 0.5f;
}

__device__ __forceinline__ void cpasync4(uint32_t saddr, const float* gptr, int vbytes) {
    asm volatile("cp.async.ca.shared.global [%0], [%1], 4, %2;"
                 :: "r"(saddr), "l"(gptr), "r"(vbytes));
}
__device__ __forceinline__ void cpcommit() {
    asm volatile("cp.async.commit_group;");
}
__device__ __forceinline__ void cpwait0() {
    asm volatile("cp.async.wait_group 0;");
}

// ============================================================================
// Kernel A: gi GEMM -> g_gi[n][t][b][GROW] fp16 via conflict-free smem swizzle.
// Also zeroes out[] (block x==0) so the fused BC kernel can atomicAdd.
// ============================================================================
#define ACH 16
#define XROW 132   // padded xs row (floats), 16B-aligned stride

__global__ void __launch_bounds__(128) gi_gemm_kernel(
    const float* __restrict__ x,
    const float* __restrict__ Wih,
    float* __restrict__ out)
{
    extern __shared__ __align__(16) float smraw[];
    float*   wd  = smraw;                    // [35][48], j consecutive
    float*   xs  = wd + 35 * 48;             // [2][35][XROW]
    __half2* osm = reinterpret_cast<__half2*>(xs + 2 * 35 * XROW); // [128][32]

    const int n   = blockIdx.y;
    const int t0  = blockIdx.x * ACH;
    const int tid = threadIdx.x;
    const int jq  = tid & 7;      // owns j = jq*6 .. jq*6+5
    const int bq  = tid >> 3;     // owns b = bq*8 .. bq*8+7
    const int swz = (bq & 7) * 4;

    if (blockIdx.x == 0) out[n * BB + tid] = 0.0f;

    const float* Wg = Wih + (size_t)n * 48 * FF;
    for (int i = tid; i < 48 * FF; i += 128)
        wd[(i % FF) * 48 + (i / FF)] = Wg[i];

    const int offs[5] = {0, -10, 1, 10, -1};
    const int s  = tid % 7;
    const int q  = tid / 7;
    const bool active = (q < 16);
    int nofs[5]; int vbytes[5];
    #pragma unroll
    for (int o = 0; o < 5; o++) {
        int n2 = n + offs[o];
        bool v = (n2 >= 0) && (n2 < NN);
        nofs[o]   = (v ? n2 : 0) * SS + s;
        vbytes[o] = v ? 4 : 0;
    }
    uint32_t xs_base = (uint32_t)__cvta_generic_to_shared(xs);

    auto stage = [&](int buf, int t) {
        if (active) {
            #pragma unroll
            for (int o = 0; o < 5; o++) {
                int f = o * 7 + s;
                #pragma unroll
                for (int bc = 0; bc < 8; bc++) {
                    int b = bc * 16 + q;
                    const float* gp = x + (size_t)b * (TT * NN * SS)
                                        + (size_t)t * (NN * SS) + nofs[o];
                    uint32_t sa = xs_base + (uint32_t)((buf * 35 * XROW + f * XROW + b) * 4);
                    cpasync4(sa, gp, vbytes[o]);
                }
            }
        }
        cpcommit();
    };

    stage(0, t0);
    cpwait0();
    __syncthreads();

    for (int tt = 0; tt < ACH; tt++) {
        const int t   = t0 + tt;
        const int cur = tt & 1;

        if (tt < ACH - 1) stage(cur ^ 1, t + 1);

        const float* xc = xs + cur * 35 * XROW;
        ull acc[3][8];
        #pragma unroll
        for (int jp = 0; jp < 3; jp++)
            #pragma unroll
            for (int b = 0; b < 8; b++) acc[jp][b] = 0ULL;

        #pragma unroll 5
        for (int f = 0; f < FF; f++) {
            const float4* xp = reinterpret_cast<const float4*>(&xc[f * XROW + bq * 8]);
            float4 xa = xp[0], xb = xp[1];
            ull xd[8] = {dup2(xa.x), dup2(xa.y), dup2(xa.z), dup2(xa.w),
                         dup2(xb.x), dup2(xb.y), dup2(xb.z), dup2(xb.w)};
            const ull* wp = reinterpret_cast<const ull*>(&wd[f * 48 + jq * 6]);
            ull w0 = wp[0], w1 = wp[1], w2 = wp[2];
            #pragma unroll
            for (int b = 0; b < 8; b++) {
                acc[0][b] = fma2(xd[b], w0, acc[0][b]);
                acc[1][b] = fma2(xd[b], w1, acc[1][b]);
                acc[2][b] = fma2(xd[b], w2, acc[2][b]);
            }
        }

        #pragma unroll
        for (int ib = 0; ib < 8; ib++) {
            __half2* row = osm + (size_t)(bq * 8 + ib) * 32;
            row[(jq * 3 + 0) ^ swz] = __floats2half2_rn(plo(acc[0][ib]), phi(acc[0][ib]));
            row[(jq * 3 + 1) ^ swz] = __floats2half2_rn(plo(acc[1][ib]), phi(acc[1][ib]));
            row[(jq * 3 + 2) ^ swz] = __floats2half2_rn(plo(acc[2][ib]), phi(acc[2][ib]));
        }
        __syncthreads();

        {
            const float4* src = reinterpret_cast<const float4*>(osm);
            float4* dst = reinterpret_cast<float4*>(
                g_gi + (size_t)(n * TT + t) * BB * GROW);
            #pragma unroll
            for (int r = 0; r < 8; r++)
                dst[r * 128 + tid] = src[r * 128 + tid];
        }

        cpwait0();
        __syncthreads();
    }
}

// ============================================================================
// Fused BC: 1600 blocks x 256 threads, role = bid & 1.
//   role B (even, 800): lm MLP for 16 batches; H1 in dyn smem [16][H1ROW];
//     layer3 via register partials + small reduction; atomicAdd f.
//   role C (odd, 800): GRU recurrence for 16 batches (8 warps, warp-local),
//     tanh.approx gates; atomicAdd q. Uses first 4KB of dyn as h-exchange.
// ============================================================================
__global__ void __launch_bounds__(256) bc_fused_kernel(
    const float* __restrict__ x,
    const float* __restrict__ W1, const float* __restrict__ b1,
    const float* __restrict__ W2, const float* __restrict__ b2,
    const float* __restrict__ W3, const float* __restrict__ b3,
    const float* __restrict__ Whh,
    const float* __restrict__ bih, const float* __restrict__ bhh,
    const float* __restrict__ scW1, const float* __restrict__ scb1,
    const float* __restrict__ scW2, const float* __restrict__ scb2,
    const float* __restrict__ scW3, const float* __restrict__ scb3,
    float* __restrict__ out)
{
    extern __shared__ __align__(16) float dyn[];   // B: H1T[16][H1ROW]; C: shf
    __shared__ __align__(16) float xlsT[FF][16];
    __shared__ __align__(16) float part[16][65];
    __shared__ float sp2[16][17];

    const int bid = blockIdx.x;
    const int tid = threadIdx.x;

    if ((bid & 1) == 0) {
        // ==================== role B: lm MLP (16 batches) ====================
        const int bidx = bid >> 1;         // 0..799
        const int n    = bidx >> 3;
        const int bh16 = (bidx & 7) * 16;
        float* H1T = dyn;                  // [16][H1ROW]
        const int offs[5] = {0, -10, 1, 10, -1};

        for (int idx = tid; idx < FF * 16; idx += 256) {
            int f = idx >> 4, b = idx & 15;
            int o = f / SS, sx = f % SS;
            int n2 = n + offs[o];
            float v = 0.0f;
            if (n2 >= 0 && n2 < NN) {
                size_t gb = (size_t)(bh16 + b);
                v = x[(gb * TT + (TT - 1)) * (NN * SS) + n2 * SS + sx];
            }
            xlsT[f][b] = v;
        }
        __syncthreads();

        // layer 1: 512h x 16b. Thread: hg=tid&63 (8 h), bg=tid>>6 (4 b).
        // acc pairs over h; stores to H1T[b][h] are lane-consecutive.
        {
            const float* W1g = W1 + (size_t)n * FF * 512;
            const float* b1g = b1 + (size_t)n * 512;
            const int hg = tid & 63;
            const int bg = tid >> 6;
            ull acc[4][4];
            #pragma unroll
            for (int b = 0; b < 4; b++)
                #pragma unroll
                for (int hp = 0; hp < 4; hp++) acc[b][hp] = 0ULL;

            #pragma unroll 5
            for (int f = 0; f < FF; f++) {
                float4 xv = *reinterpret_cast<const float4*>(&xlsT[f][bg * 4]);
                ull xd[4] = {dup2(xv.x), dup2(xv.y), dup2(xv.z), dup2(xv.w)};
                const ull* wp = reinterpret_cast<const ull*>(W1g + f * 512 + hg * 8);
                ull w0 = wp[0], w1 = wp[1], w2 = wp[2], w3 = wp[3];
                #pragma unroll
                for (int b = 0; b < 4; b++) {
                    acc[b][0] = fma2(xd[b], w0, acc[b][0]);
                    acc[b][1] = fma2(xd[b], w1, acc[b][1]);
                    acc[b][2] = fma2(xd[b], w2, acc[b][2]);
                    acc[b][3] = fma2(xd[b], w3, acc[b][3]);
                }
            }
            const float4* bp = reinterpret_cast<const float4*>(b1g + hg * 8);
            float4 ba = bp[0], bb = bp[1];
            float bias[8] = {ba.x, ba.y, ba.z, ba.w, bb.x, bb.y, bb.z, bb.w};
            #pragma unroll
            for (int b = 0; b < 4; b++) {
                float v[8];
                #pragma unroll
                for (int hp = 0; hp < 4; hp++) {
                    v[2*hp]   = fmaxf(plo(acc[b][hp]) + bias[2*hp],   0.0f);
                    v[2*hp+1] = fmaxf(phi(acc[b][hp]) + bias[2*hp+1], 0.0f);
                }
                float* row = &H1T[(size_t)(bg * 4 + b) * H1ROW + hg * 8];
                reinterpret_cast<float4*>(row)[0] = make_float4(v[0], v[1], v[2], v[3]);
                reinterpret_cast<float4*>(row)[1] = make_float4(v[4], v[5], v[6], v[7]);
            }
        }
        __syncthreads();

        // layer 2 + 3: 256h x 16b, layer3 folded into registers.
        {
            const float* W2g = W2 + (size_t)n * 512 * 256;
            const int hg = tid & 63;   // 4 h = hg*4
            const int bg = tid >> 6;   // 4 b = bg*4
            ull acc2[4][2];
            #pragma unroll
            for (int b = 0; b < 4; b++) { acc2[b][0] = 0ULL; acc2[b][1] = 0ULL; }

            #pragma unroll 2
            for (int f4 = 0; f4 < 128; f4++) {
                ull w[4][2];
                #pragma unroll
                for (int ff = 0; ff < 4; ff++) {
                    const ull* wp = reinterpret_cast<const ull*>(
                        W2g + (size_t)(f4 * 4 + ff) * 256 + hg * 4);
                    w[ff][0] = wp[0]; w[ff][1] = wp[1];
                }
                float4 h1v[4];
                #pragma unroll
                for (int b = 0; b < 4; b++)
                    h1v[b] = *reinterpret_cast<const float4*>(
                        &H1T[(size_t)(bg * 4 + b) * H1ROW + f4 * 4]);
                #pragma unroll
                for (int ff = 0; ff < 4; ff++) {
                    #pragma unroll
                    for (int b = 0; b < 4; b++) {
                        float hv = reinterpret_cast<const float*>(&h1v[b])[ff];
                        ull xd = dup2(hv);
                        acc2[b][0] = fma2(xd, w[ff][0], acc2[b][0]);
                        acc2[b][1] = fma2(xd, w[ff][1], acc2[b][1]);
                    }
                }
            }

            float4 b2v = *reinterpret_cast<const float4*>(b2 + (size_t)n * 256 + hg * 4);
            float4 w3v = *reinterpret_cast<const float4*>(W3 + (size_t)n * 256 + hg * 4);
            #pragma unroll
            for (int b = 0; b < 4; b++) {
                float v0 = fmaxf(plo(acc2[b][0]) + b2v.x, 0.0f);
                float v1 = fmaxf(phi(acc2[b][0]) + b2v.y, 0.0f);
                float v2 = fmaxf(plo(acc2[b][1]) + b2v.z, 0.0f);
                float v3 = fmaxf(phi(acc2[b][1]) + b2v.w, 0.0f);
                part[bg * 4 + b][hg] = v0 * w3v.x + v1 * w3v.y + v2 * w3v.z + v3 * w3v.w;
            }
        }
        __syncthreads();

        {
            int rb = tid >> 4, seg = tid & 15;
            float s = part[rb][seg * 4 + 0] + part[rb][seg * 4 + 1]
                    + part[rb][seg * 4 + 2] + part[rb][seg * 4 + 3];
            sp2[rb][seg] = s;
        }
        __syncthreads();
        if (tid < 16) {
            float tot = b3[n];
            #pragma unroll
            for (int seg = 0; seg < 16; seg++) tot += sp2[tid][seg];
            atomicAdd(&out[n * BB + bh16 + tid], tot);
        }
    } else {
        // ==================== role C: GRU recurrence ====================
        const int cidx  = bid >> 1;        // 0..799
        const int n     = cidx >> 3;
        const int bbase = (cidx & 7) * 16;

        float (*shf)[2][2][16] = reinterpret_cast<float(*)[2][2][16]>(dyn); // [8 warps]

        const int w    = tid >> 5;
        const int lane = tid & 31;
        const int j    = lane & 15;
        const int bh   = lane >> 4;
        const int bglob = bbase + w * 2 + bh;

        const ull* wrp = reinterpret_cast<const ull*>(Whh + ((size_t)n * 48 + j     ) * GG);
        const ull* wzp = reinterpret_cast<const ull*>(Whh + ((size_t)n * 48 + j + 16) * GG);
        const ull* wnp = reinterpret_cast<const ull*>(Whh + ((size_t)n * 48 + j + 32) * GG);
        ull wr[8], wz[8], wn[8];
        #pragma unroll
        for (int k = 0; k < 8; k++) { wr[k] = wrp[k]; wz[k] = wzp[k]; wn[k] = wnp[k]; }

        const float br  = bih[n * 48 + j     ] + bhh[n * 48 + j     ];
        const float bz  = bih[n * 48 + j + 16] + bhh[n * 48 + j + 16];
        const float bin = bih[n * 48 + j + 32];
        const float bhn = bhh[n * 48 + j + 32];

        const int sw  = ((bglob >> 3) & 7) * 4;
        const int o_r = (((j      ) >> 1) ^ sw) * 2 + (j & 1);
        const int o_z = (((j + 16 ) >> 1) ^ sw) * 2 + (j & 1);
        const int o_n = (((j + 32 ) >> 1) ^ sw) * 2 + (j & 1);

        shf[w][0][bh][j] = 0.0f;
        float hreg = 0.0f;
        __syncwarp();

        const __half* gbase = g_gi + ((size_t)n * TT * BB + bglob) * GROW;
        float gir = __half2float(gbase[o_r]);
        float giz = __half2float(gbase[o_z]);
        float gin = __half2float(gbase[o_n]);

        int cur = 0;
        for (int t = 0; t < TT; t++) {
            const __half* grn = gbase + (size_t)((t + 1 < TT) ? t + 1 : t) * BB * GROW;
            float pgr = __half2float(grn[o_r]);
            float pgz = __half2float(grn[o_z]);
            float pgn = __half2float(grn[o_n]);

            const ull* hp = reinterpret_cast<const ull*>(&shf[w][cur][bh][0]);
            ull ar = 0ULL, az = 0ULL, an = 0ULL;
            #pragma unroll
            for (int k = 0; k < 8; k++) {
                ull hk = hp[k];
                ar = fma2(hk, wr[k], ar);
                az = fma2(hk, wz[k], az);
                an = fma2(hk, wn[k], an);
            }
            float r  = sighw(br + gir + plo(ar) + phi(ar));
            float z  = sighw(bz + giz + plo(az) + phi(az));
            float nv = tanhhw(bin + gin + r * (bhn + plo(an) + phi(an)));
            float hnew = nv + z * (hreg - nv);
            hreg = hnew;
            shf[w][cur ^ 1][bh][j] = hnew;
            __syncwarp();
            gir = pgr; giz = pgz; gin = pgn;
            cur ^= 1;
        }

        // sc MLP epilogue
        shf[w][0][bh][j] = hreg;
        __syncwarp();
        {
            float a = scb1[n * GG + j];
            #pragma unroll
            for (int k = 0; k < GG; k++)
                a = fmaf(shf[w][0][bh][k], scW1[((size_t)n * GG + k) * GG + j], a);
            shf[w][1][bh][j] = fmaxf(a, 0.0f);
        }
        __syncwarp();
        {
            float a = scb2[n * GG + j];
            #pragma unroll
            for (int k = 0; k < GG; k++)
                a = fmaf(shf[w][1][bh][k], scW2[((size_t)n * GG + k) * GG + j], a);
            shf[w][0][bh][j] = fmaxf(a, 0.0f);
        }
        __syncwarp();
        if (j == 0) {
            float q = scb3[n];
            #pragma unroll
            for (int k = 0; k < GG; k++)
                q = fmaf(shf[w][0][bh][k], scW3[n * GG + k], q);
            atomicAdd(&out[n * BB + bglob], q);
        }
    }
}

// ============================================================================
extern "C" void kernel_launch(void* const* d_in, const int* in_sizes, int n_in,
                              void* d_out, int out_size) {
    const float* x      = (const float*)d_in[0];
    const float* lm_W1  = (const float*)d_in[1];
    const float* lm_b1  = (const float*)d_in[2];
    const float* lm_W2  = (const float*)d_in[3];
    const float* lm_b2  = (const float*)d_in[4];
    const float* lm_W3  = (const float*)d_in[5];
    const float* lm_b3  = (const float*)d_in[6];
    const float* gWih   = (const float*)d_in[7];
    const float* gWhh   = (const float*)d_in[8];
    const float* gbih   = (const float*)d_in[9];
    const float* gbhh   = (const float*)d_in[10];
    const float* scW1   = (const float*)d_in[11];
    const float* scb1   = (const float*)d_in[12];
    const float* scW2   = (const float*)d_in[13];
    const float* scb2   = (const float*)d_in[14];
    const float* scW3   = (const float*)d_in[15];
    const float* scb3   = (const float*)d_in[16];
    float* out = (float*)d_out;

    const int bc_bytes = 16 * H1ROW * 4;                             // 33280
    const int a_bytes  = (35*48 + 2*35*XROW) * 4 + 128 * 32 * 4;     // 60064
    cudaFuncSetAttribute(bc_fused_kernel,
                         cudaFuncAttributeMaxDynamicSharedMemorySize, bc_bytes);
    cudaFuncSetAttribute(gi_gemm_kernel,
                         cudaFuncAttributeMaxDynamicSharedMemorySize, a_bytes);

    // A: gi GEMM (+ zero out)
    dim3 gridA(TT / ACH, NN), blockA(128);
    gi_gemm_kernel<<<gridA, blockA, a_bytes>>>(x, gWih, out);

    // BC fused: lm MLP + GRU recurrence, co-scheduled at high occupancy
    bc_fused_kernel<<<1600, 256, bc_bytes>>>(
        x, lm_W1, lm_b1, lm_W2, lm_b2, lm_W3, lm_b3,
        gWhh, gbih, gbhh,
        scW1, scb1, scW2, scb2, scW3, scb3, out);
}